// round 9
// baseline (speedup 1.0000x reference)
#include <cuda_runtime.h>
#include <cuda_bf16.h>
#include <cstdint>
#include <math.h>

#define BATCH 16
#define SEQ   512
#define NI    32
#define NHEAD 8
#define NH    512
#define NO    64
#define MROWS (BATCH*SEQ)      // 8192
#define VDIM  (NHEAD*NI)       // 256
#define EPSV  1e-5f
#define SLOPE 0.05f
#define NPART 64

// ---------------- scratch ----------------
__device__ float    g_En  [16*8*512];
__device__ uint32_t g_Xthi[(size_t)16*256*256], g_Xtlo[(size_t)16*256*256];
__device__ uint32_t g_Ghi [(size_t)16*512*256], g_Glo [(size_t)16*512*256];
__device__ uint32_t g_Vhi [(size_t)8192*128],   g_Vlo [(size_t)8192*128];
__device__ uint32_t g_W1hi[512*128], g_W1lo[512*128];
// int8 weights (2 digits) + per-row scales
__device__ uint32_t g_W2q1[512*128], g_W2q0[512*128];
__device__ uint32_t g_W3q1[64*128],  g_W3q0[64*128];
__device__ float    g_tW2[512], g_tW3[64];
// int8 activations (2 digits) + per-row scales
__device__ uint32_t g_Aq1[(size_t)8192*128], g_Aq0[(size_t)8192*128];
__device__ float    g_rs[8192];
__device__ float g_Y1[(size_t)MROWS * NH];
__device__ float g_Y2[(size_t)MROWS * NH];
__device__ float g_Y3[(size_t)MROWS * NO];
__device__ float g_pS [NPART * NH];
__device__ float g_pS2[NPART * NH];
__device__ float g_scale[NH];
__device__ float g_shift[NH];

// ---------------- helpers ----------------
__device__ __forceinline__ void split_pair(float v0, float v1, uint32_t& hi, uint32_t& lo) {
    __nv_bfloat16 h0 = __float2bfloat16(v0);
    __nv_bfloat16 h1 = __float2bfloat16(v1);
    float r0 = v0 - __bfloat162float(h0);
    float r1 = v1 - __bfloat162float(h1);
    __nv_bfloat16 l0 = __float2bfloat16(r0);
    __nv_bfloat16 l1 = __float2bfloat16(r1);
    hi = ((uint32_t)__bfloat16_as_ushort(h1) << 16) | __bfloat16_as_ushort(h0);
    lo = ((uint32_t)__bfloat16_as_ushort(l1) << 16) | __bfloat16_as_ushort(l0);
}

__device__ __forceinline__ void mma_bf16(float* d, const uint32_t* a, const uint32_t* b) {
    asm volatile(
        "mma.sync.aligned.m16n8k16.row.col.f32.bf16.bf16.f32 "
        "{%0,%1,%2,%3}, {%4,%5,%6,%7}, {%8,%9}, {%0,%1,%2,%3};"
        : "+f"(d[0]), "+f"(d[1]), "+f"(d[2]), "+f"(d[3])
        : "r"(a[0]), "r"(a[1]), "r"(a[2]), "r"(a[3]), "r"(b[0]), "r"(b[1]));
}

__device__ __forceinline__ void mma_s8(int* d, const uint32_t* a, const uint32_t* b) {
    asm volatile(
        "mma.sync.aligned.m16n8k32.row.col.s32.s8.s8.s32 "
        "{%0,%1,%2,%3}, {%4,%5,%6,%7}, {%8,%9}, {%0,%1,%2,%3};"
        : "+r"(d[0]), "+r"(d[1]), "+r"(d[2]), "+r"(d[3])
        : "r"(a[0]), "r"(a[1]), "r"(a[2]), "r"(a[3]), "r"(b[0]), "r"(b[1]));
}

__device__ __forceinline__ void ldsm4(uint32_t* r, uint32_t addr) {
    asm volatile("ldmatrix.sync.aligned.m8n8.x4.shared.b16 {%0,%1,%2,%3}, [%4];"
        : "=r"(r[0]), "=r"(r[1]), "=r"(r[2]), "=r"(r[3]) : "r"(addr));
}

__device__ __forceinline__ uint32_t smem_u32(const void* p) {
    uint32_t a;
    asm("{ .reg .u64 t; cvta.to.shared.u64 t, %1; cvt.u32.u64 %0, t; }" : "=r"(a) : "l"(p));
    return a;
}
__device__ __forceinline__ void cp_async16(uint32_t saddr, const void* gptr) {
    asm volatile("cp.async.cg.shared.global [%0], [%1], 16;" :: "r"(saddr), "l"(gptr));
}
#define CP_COMMIT() asm volatile("cp.async.commit_group;" ::: "memory")
#define CP_WAIT0()  asm volatile("cp.async.wait_group 0;" ::: "memory")

__device__ __forceinline__ uint32_t pack4(const int* d) {
    return (uint32_t)(uint8_t)(int8_t)d[0] | ((uint32_t)(uint8_t)(int8_t)d[1] << 8)
         | ((uint32_t)(uint8_t)(int8_t)d[2] << 16) | ((uint32_t)(uint8_t)(int8_t)d[3] << 24);
}
__device__ __forceinline__ float warp_max(float v) {
    #pragma unroll
    for (int off = 16; off > 0; off >>= 1)
        v = fmaxf(v, __shfl_xor_sync(0xffffffffu, v, off));
    return v;
}

// ---------------- prep: En/Xt + W1 bf16 split + W2/W3 int8 digits ----------------
__global__ void __launch_bounds__(256) prep_kernel(
    const float* __restrict__ x, const float* __restrict__ Q,
    float* __restrict__ En,
    uint32_t* __restrict__ Xthi, uint32_t* __restrict__ Xtlo,
    const float* __restrict__ W1, uint32_t* __restrict__ W1hi, uint32_t* __restrict__ W1lo,
    const float* __restrict__ W2, uint32_t* __restrict__ W2q1, uint32_t* __restrict__ W2q0,
    float* __restrict__ tW2,
    const float* __restrict__ W3, uint32_t* __restrict__ W3q1, uint32_t* __restrict__ W3q0,
    float* __restrict__ tW3)
{
    const int blk = blockIdx.x;
    const int tid = threadIdx.x;

    if (blk >= 64) {
        int widx = blk - 64;
        if (widx < 32) {
            // W1 bf16 split
            int base = widx * 2048;
            int p = base + tid;
            #pragma unroll
            for (int j = 0; j < 8; j++, p += 256) {
                float2 v = ((const float2*)W1)[p];
                uint32_t h, l; split_pair(v.x, v.y, h, l);
                W1hi[p] = h; W1lo[p] = l;
            }
        } else {
            // int8 2-digit quantization, one warp -> rows
            const int w = tid >> 5, l = tid & 31;
            const float* Wsrc; uint32_t* q1; uint32_t* q0; float* tW;
            int row0, nrows;
            if (widx < 64) { Wsrc = W2; q1 = W2q1; q0 = W2q0; tW = tW2; row0 = (widx-32)*16 + w*2; nrows = 2; }
            else           { Wsrc = W3; q1 = W3q1; q0 = W3q0; tW = tW3; row0 = (widx-64)*8 + w;    nrows = 1; }
            for (int rr = 0; rr < nrows; rr++) {
                int row = row0 + rr;
                const float* wp = Wsrc + (size_t)row * 512 + l * 16;
                float v[16]; float mx = 1e-20f;
                #pragma unroll
                for (int e = 0; e < 16; e++) { v[e] = wp[e]; mx = fmaxf(mx, fabsf(v[e])); }
                mx = warp_max(mx);
                if (l == 0) tW[row] = mx;
                float inv = 127.f / mx;
                #pragma unroll
                for (int c = 0; c < 4; c++) {
                    int d1[4], d0[4];
                    #pragma unroll
                    for (int e = 0; e < 4; e++) {
                        float s = v[c*4+e] * inv;
                        float f1 = rintf(s);
                        d1[e] = (int)f1;
                        d0[e] = (int)rintf((s - f1) * 254.f);
                    }
                    q1[(size_t)row*128 + l*4 + c] = pack4(d1);
                    q0[(size_t)row*128 + l*4 + c] = pack4(d0);
                }
            }
        }
        return;
    }

    const int b = blk >> 2, chunk = blk & 3;

    __shared__ float sEm[8][128];
    __shared__ float sQ[8][4];
    __shared__ uint32_t shi[256][8], slo[256][8];

    if (tid < 8) {
        float a = Q[tid*3+0], bq = Q[tid*3+1], cq = Q[tid*3+2];
        sQ[tid][0] = a; sQ[tid][1] = bq; sQ[tid][2] = cq;
        sQ[tid][3] = a*a + bq*bq + cq*cq;
    }
    __syncthreads();

    if (tid < 128) {
        int m = chunk*128 + tid;
        const float* xp = x + ((size_t)b*512 + m)*32;
        float px = xp[0], py = xp[1], pz = xp[2];
        #pragma unroll
        for (int h = 0; h < 8; h++) {
            float dot = px*sQ[h][0] + py*sQ[h][1] + pz*sQ[h][2];
            float em = __expf(-2.f*dot);
            float en = __expf(2.f*dot - sQ[h][3]);
            sEm[h][tid] = em;
            En[((size_t)b*8 + h)*512 + m] = en;
        }
    }
    __syncthreads();

    const int c = tid, h = c >> 5, i = c & 31;
    for (int grp = 0; grp < 8; grp++) {
        #pragma unroll
        for (int j = 0; j < 8; j++) {
            int mloc = (grp*8 + j)*2;
            int m = chunk*128 + mloc;
            float v0 = sEm[h][mloc]   * x[((size_t)b*512 + m  )*32 + i];
            float v1 = sEm[h][mloc+1] * x[((size_t)b*512 + m+1)*32 + i];
            uint32_t hh, ll; split_pair(v0, v1, hh, ll);
            shi[c][j] = hh; slo[c][j] = ll;
        }
        __syncthreads();
        int cc = tid >> 3, j2 = tid & 7;
        #pragma unroll
        for (int rep = 0; rep < 8; rep++) {
            int ccc = cc + rep*32;
            size_t addr = ((size_t)b*256 + ccc)*256 + chunk*64 + grp*8 + j2;
            Xthi[addr] = shi[ccc][j2];
            Xtlo[addr] = slo[ccc][j2];
        }
        __syncthreads();
    }
}

// ---------------- buildG ----------------
__global__ void __launch_bounds__(256) buildG_kernel(
    const float* __restrict__ x, uint32_t* __restrict__ Ghi, uint32_t* __restrict__ Glo)
{
    const int b  = blockIdx.x >> 3, nt = blockIdx.x & 7;
    const int tid = threadIdx.x;
    const int n = tid & 63, mq = tid >> 6;

    __shared__ float pn3[64][5];
    __shared__ float pm3[128][4];

    if (tid < 64) {
        const float* xp = x + ((size_t)b*512 + nt*64 + tid)*32;
        pn3[tid][0] = xp[0]; pn3[tid][1] = xp[1]; pn3[tid][2] = xp[2];
    }

    for (int mc = 0; mc < 4; mc++) {
        __syncthreads();
        if (tid < 128) {
            const float* xp = x + ((size_t)b*512 + mc*128 + tid)*32;
            pm3[tid][0] = xp[0]; pm3[tid][1] = xp[1]; pm3[tid][2] = xp[2];
        }
        __syncthreads();
        float px = pn3[n][0], py = pn3[n][1], pz = pn3[n][2];
        uint32_t outh[16], outl[16];
        #pragma unroll
        for (int j = 0; j < 16; j++) {
            int ml = mq*32 + j*2;
            float dx0 = px - pm3[ml][0],   dy0 = py - pm3[ml][1],   dz0 = pz - pm3[ml][2];
            float dx1 = px - pm3[ml+1][0], dy1 = py - pm3[ml+1][1], dz1 = pz - pm3[ml+1][2];
            float e0 = __expf(-(dx0*dx0 + dy0*dy0 + dz0*dz0));
            float e1 = __expf(-(dx1*dx1 + dy1*dy1 + dz1*dz1));
            split_pair(e0, e1, outh[j], outl[j]);
        }
        size_t base = ((size_t)b*512 + nt*64 + n)*256 + mc*64 + mq*16;
        #pragma unroll
        for (int j4 = 0; j4 < 4; j4++) {
            ((uint4*)(Ghi + base))[j4] = make_uint4(outh[j4*4], outh[j4*4+1], outh[j4*4+2], outh[j4*4+3]);
            ((uint4*)(Glo + base))[j4] = make_uint4(outl[j4*4], outl[j4*4+1], outl[j4*4+2], outl[j4*4+3]);
        }
    }
}

// ================= GEMM machinery: K32(bf16)/K64(i8) tiles, 2-stage, RSU=20 =================
#define RSU 20

// ---------------- vgemm (bf16 pair): V = En .* (G @ Xt^T) - pos, TN=64 ----------------
__global__ void __launch_bounds__(256, 2) vgemm_kernel(
    const uint32_t* __restrict__ Ghi, const uint32_t* __restrict__ Glo,
    const uint32_t* __restrict__ Bhi_g, const uint32_t* __restrict__ Blo_g,
    const float* __restrict__ En, const float* __restrict__ x,
    uint32_t* __restrict__ Vhi, uint32_t* __restrict__ Vlo)
{
    constexpr int TN = 64, NFRAG = TN/16, KE = 512, K2 = KE/2;
    constexpr int ASZ = 128*RSU, BSZ = TN*RSU;
    extern __shared__ uint32_t smem_u[];
    const uint32_t sbase = smem_u32(smem_u);
    const uint32_t bAh = sbase;
    const uint32_t bAl = sbase + 2*ASZ*4;
    const uint32_t bBh = sbase + 4*ASZ*4;
    const uint32_t bBl = sbase + (4*ASZ + 2*BSZ)*4;

    const int tid = threadIdx.x, wid = tid >> 5, lane = tid & 31;
    const int wm = (wid >> 1) * 32, wn = (wid & 1) * (TN/2);
    const int l4 = lane >> 2, lk = lane & 3;
    const int rowA = lane & 15, colA = (lane >> 4) * 4;
    const int rowB = ((lane >> 4) & 1) * 8 + (lane & 7);
    const int colB = ((lane >> 3) & 1) * 4;
    const int b = blockIdx.z;
    const int m0 = blockIdx.y * 128, c0 = blockIdx.x * TN;

    const uint32_t* Ah_g = Ghi + (size_t)b*512*K2;
    const uint32_t* Al_g = Glo + (size_t)b*512*K2;
    const uint32_t* Bh_g = Bhi_g + (size_t)b*256*K2;
    const uint32_t* Bl_g = Blo_g + (size_t)b*256*K2;

    float acc[2][NFRAG][4];
    #pragma unroll
    for (int a = 0; a < 2; a++)
        #pragma unroll
        for (int q = 0; q < NFRAG; q++)
            { acc[a][q][0]=0.f; acc[a][q][1]=0.f; acc[a][q][2]=0.f; acc[a][q][3]=0.f; }

    auto issue = [&](int t) {
        int buf = t & 1;
        #pragma unroll
        for (int j = 0; j < 2; j++) {
            int lin = tid + j*256; int r = lin >> 2, q = lin & 3;
            uint32_t off = (uint32_t)(buf*ASZ + r*RSU + q*4) * 4;
            size_t ao = (size_t)(m0 + r)*K2 + t*16 + q*4;
            cp_async16(bAh + off, Ah_g + ao);
            cp_async16(bAl + off, Al_g + ao);
        }
        {
            int r = tid >> 2, q = tid & 3;
            uint32_t off = (uint32_t)(buf*BSZ + r*RSU + q*4) * 4;
            size_t bo = (size_t)(c0 + r)*K2 + t*16 + q*4;
            cp_async16(bBh + off, Bh_g + bo);
            cp_async16(bBl + off, Bl_g + bo);
        }
        CP_COMMIT();
    };

    auto compute = [&](int buf) {
        #pragma unroll
        for (int kk = 0; kk < 2; kk++) {
            uint32_t ah[2][4], al[2][4];
            #pragma unroll
            for (int mi = 0; mi < 2; mi++) {
                uint32_t off = (uint32_t)(buf*ASZ + (wm + mi*16 + rowA)*RSU + kk*8 + colA) * 4;
                ldsm4(ah[mi], bAh + off);
                ldsm4(al[mi], bAl + off);
            }
            #pragma unroll
            for (int np = 0; np < NFRAG/2; np++) {
                uint32_t off = (uint32_t)(buf*BSZ + (wn + np*16 + rowB)*RSU + kk*8 + colB) * 4;
                uint32_t th[4], tl[4];
                ldsm4(th, bBh + off);
                ldsm4(tl, bBl + off);
                #pragma unroll
                for (int sub = 0; sub < 2; sub++) {
                    int ni = np*2 + sub;
                    uint32_t bhp[2] = {th[sub*2], th[sub*2+1]};
                    uint32_t blp[2] = {tl[sub*2], tl[sub*2+1]};
                    #pragma unroll
                    for (int mi = 0; mi < 2; mi++) {
                        mma_bf16(acc[mi][ni], ah[mi], bhp);
                        mma_bf16(acc[mi][ni], ah[mi], blp);
                        mma_bf16(acc[mi][ni], al[mi], bhp);
                    }
                }
            }
        }
    };

    const int T = KE / 32;
    issue(0);
    for (int t = 0; t < T; t++) {
        CP_WAIT0();
        __syncthreads();
        if (t + 1 < T) issue(t + 1);
        compute(t & 1);
    }

    #pragma unroll
    for (int mi = 0; mi < 2; mi++) {
        #pragma unroll
        for (int ni = 0; ni < NFRAG; ni++) {
            int n0 = m0 + wm + mi*16 + l4;
            int cc = c0 + wn + ni*8 + lk*2;
            int h = cc >> 5, il = cc & 31;
            float en0 = En[((size_t)b*8 + h)*512 + n0];
            float en1 = En[((size_t)b*8 + h)*512 + n0 + 8];
            float v00 = acc[mi][ni][0]*en0, v01 = acc[mi][ni][1]*en0;
            float v10 = acc[mi][ni][2]*en1, v11 = acc[mi][ni][3]*en1;
            if (il < 3) {
                v00 -= x[((size_t)b*512 + n0  )*32 + il];
                v10 -= x[((size_t)b*512 + n0+8)*32 + il];
            }
            if (il + 1 < 3) {
                v01 -= x[((size_t)b*512 + n0  )*32 + il + 1];
                v11 -= x[((size_t)b*512 + n0+8)*32 + il + 1];
            }
            uint32_t h0, l0, h1, l1;
            split_pair(v00, v01, h0, l0);
            split_pair(v10, v11, h1, l1);
            size_t r0 = ((size_t)b*512 + n0)*128 + (cc >> 1);
            size_t r1 = ((size_t)b*512 + n0 + 8)*128 + (cc >> 1);
            Vhi[r0] = h0; Vlo[r0] = l0;
            Vhi[r1] = h1; Vlo[r1] = l1;
        }
    }
}

// ---------------- gemm_ps (bf16 pair) + fused stats: layer 1 ----------------
template<int TN>
__global__ void __launch_bounds__(256, 2) gemm_ps_kernel(
    const uint32_t* __restrict__ Ah_g, const uint32_t* __restrict__ Al_g,
    const uint32_t* __restrict__ Bh_g, const uint32_t* __restrict__ Bl_g,
    const float* __restrict__ bias, float* __restrict__ Y,
    float* __restrict__ pS, float* __restrict__ pS2, int K, int C)
{
    constexpr int NFRAG = TN/16;
    constexpr int BLD = TN/64;
    constexpr int ASZ = 128*RSU, BSZ = TN*RSU;
    extern __shared__ uint32_t smem_u[];
    const uint32_t sbase = smem_u32(smem_u);
    const uint32_t bAh = sbase;
    const uint32_t bAl = sbase + 2*ASZ*4;
    const uint32_t bBh = sbase + 4*ASZ*4;
    const uint32_t bBl = sbase + (4*ASZ + 2*BSZ)*4;

    const int tid = threadIdx.x, wid = tid >> 5, lane = tid & 31;
    const int wm = (wid >> 1) * 32, wn = (wid & 1) * (TN/2);
    const int mw = wid >> 1;
    const int l4 = lane >> 2, lk = lane & 3;
    const int rowA = lane & 15, colA = (lane >> 4) * 4;
    const int rowB = ((lane >> 4) & 1) * 8 + (lane & 7);
    const int colB = ((lane >> 3) & 1) * 4;
    const int m0 = blockIdx.y * 128, c0 = blockIdx.x * TN;
    const int K2 = K >> 1;

    float acc[2][NFRAG][4];
    #pragma unroll
    for (int a = 0; a < 2; a++)
        #pragma unroll
        for (int q = 0; q < NFRAG; q++)
            { acc[a][q][0]=0.f; acc[a][q][1]=0.f; acc[a][q][2]=0.f; acc[a][q][3]=0.f; }

    auto issue = [&](int t) {
        int buf = t & 1;
        #pragma unroll
        for (int j = 0; j < 2; j++) {
            int lin = tid + j*256; int r = lin >> 2, q = lin & 3;
            uint32_t off = (uint32_t)(buf*ASZ + r*RSU + q*4) * 4;
            size_t ao = (size_t)(m0 + r)*K2 + t*16 + q*4;
            cp_async16(bAh + off, Ah_g + ao);
            cp_async16(bAl + off, Al_g + ao);
        }
        #pragma unroll
        for (int j = 0; j < BLD; j++) {
            int lin = tid + j*256; int r = lin >> 2, q = lin & 3;
            uint32_t off = (uint32_t)(buf*BSZ + r*RSU + q*4) * 4;
            size_t bo = (size_t)(c0 + r)*K2 + t*16 + q*4;
            cp_async16(bBh + off, Bh_g + bo);
            cp_async16(bBl + off, Bl_g + bo);
        }
        CP_COMMIT();
    };

    auto compute = [&](int buf) {
        #pragma unroll
        for (int kk = 0; kk < 2; kk++) {
            uint32_t ah[2][4], al[2][4];
            #pragma unroll
            for (int mi = 0; mi < 2; mi++) {
                uint32_t off = (uint32_t)(buf*ASZ + (wm + mi*16 + rowA)*RSU + kk*8 + colA) * 4;
                ldsm4(ah[mi], bAh + off);
                ldsm4(al[mi], bAl + off);
            }
            #pragma unroll
            for (int np = 0; np < NFRAG/2; np++) {
                uint32_t off = (uint32_t)(buf*BSZ + (wn + np*16 + rowB)*RSU + kk*8 + colB) * 4;
                uint32_t th[4], tl[4];
                ldsm4(th, bBh + off);
                ldsm4(tl, bBl + off);
                #pragma unroll
                for (int sub = 0; sub < 2; sub++) {
                    int ni = np*2 + sub;
                    uint32_t bhp[2] = {th[sub*2], th[sub*2+1]};
                    uint32_t blp[2] = {tl[sub*2], tl[sub*2+1]};
                    #pragma unroll
                    for (int mi = 0; mi < 2; mi++) {
                        mma_bf16(acc[mi][ni], ah[mi], bhp);
                        mma_bf16(acc[mi][ni], ah[mi], blp);
                        mma_bf16(acc[mi][ni], al[mi], bhp);
                    }
                }
            }
        }
    };

    const int T = K / 32;
    issue(0);
    for (int t = 0; t < T; t++) {
        CP_WAIT0();
        __syncthreads();
        if (t + 1 < T) issue(t + 1);
        compute(t & 1);
    }
    __syncthreads();

    float* sbufS  = (float*)smem_u;
    float* sbufS2 = sbufS + 4*TN;

    #pragma unroll
    for (int ni = 0; ni < NFRAG; ni++) {
        int col = c0 + wn + ni*8 + lk*2;
        float2 b2 = *(const float2*)(bias + col);
        float s0 = 0.f, s1 = 0.f, q0 = 0.f, q1 = 0.f;
        #pragma unroll
        for (int mi = 0; mi < 2; mi++) {
            int row = m0 + wm + mi*16 + l4;
            float e0 = acc[mi][ni][0] + b2.x;
            float e1 = acc[mi][ni][1] + b2.y;
            float e2 = acc[mi][ni][2] + b2.x;
            float e3 = acc[mi][ni][3] + b2.y;
            *(float2*)(Y + (size_t)row * C + col)       = make_float2(e0, e1);
            *(float2*)(Y + (size_t)(row + 8) * C + col) = make_float2(e2, e3);
            s0 += e0 + e2; s1 += e1 + e3;
            q0 += e0*e0 + e2*e2; q1 += e1*e1 + e3*e3;
        }
        #pragma unroll
        for (int off = 16; off >= 4; off >>= 1) {
            s0 += __shfl_down_sync(0xffffffffu, s0, off);
            s1 += __shfl_down_sync(0xffffffffu, s1, off);
            q0 += __shfl_down_sync(0xffffffffu, q0, off);
            q1 += __shfl_down_sync(0xffffffffu, q1, off);
        }
        if (lane < 4) {
            int cb = wn + ni*8 + lk*2;
            sbufS [mw*TN + cb]     = s0;
            sbufS [mw*TN + cb + 1] = s1;
            sbufS2[mw*TN + cb]     = q0;
            sbufS2[mw*TN + cb + 1] = q1;
        }
    }
    __syncthreads();
    if (tid < TN) {
        float s = sbufS [tid] + sbufS [TN + tid] + sbufS [2*TN + tid] + sbufS [3*TN + tid];
        float q = sbufS2[tid] + sbufS2[TN + tid] + sbufS2[2*TN + tid] + sbufS2[3*TN + tid];
        pS [blockIdx.y * C + c0 + tid] = s;
        pS2[blockIdx.y * C + c0 + tid] = q;
    }
}

// ---------------- gemm_i8: int8 2-digit GEMM + fused stats (layers 2,3) ----------------
// Y[m][c] = bias[c] + srow[m]*tcol[c]/127^2 * (acc1 + accX/254)
__global__ void __launch_bounds__(256, 2) gemm_i8_kernel(
    const uint32_t* __restrict__ Aq1, const uint32_t* __restrict__ Aq0,
    const uint32_t* __restrict__ Bq1, const uint32_t* __restrict__ Bq0,
    const float* __restrict__ srow, const float* __restrict__ tcol,
    const float* __restrict__ bias, float* __restrict__ Y,
    float* __restrict__ pS, float* __restrict__ pS2, int K, int C)
{
    constexpr int TN = 64, NFRAG = TN/16;
    constexpr int ASZ = 128*RSU, BSZ = TN*RSU;
    extern __shared__ uint32_t smem_u[];
    const uint32_t sbase = smem_u32(smem_u);
    const uint32_t bA1 = sbase;
    const uint32_t bA0 = sbase + 2*ASZ*4;
    const uint32_t bB1 = sbase + 4*ASZ*4;
    const uint32_t bB0 = sbase + (4*ASZ + 2*BSZ)*4;

    const int tid = threadIdx.x, wid = tid >> 5, lane = tid & 31;
    const int wm = (wid >> 1) * 32, wn = (wid & 1) * (TN/2);
    const int mw = wid >> 1;
    const int l4 = lane >> 2, lk = lane & 3;
    const int rowA = lane & 15, colA = (lane >> 4) * 4;
    const int rowB = ((lane >> 4) & 1) * 8 + (lane & 7);
    const int colB = ((lane >> 3) & 1) * 4;
    const int m0 = blockIdx.y * 128, c0 = blockIdx.x * TN;
    const int K4 = K >> 2;   // u32 per row

    int acc1[2][NFRAG][4], accX[2][NFRAG][4];
    #pragma unroll
    for (int a = 0; a < 2; a++)
        #pragma unroll
        for (int q = 0; q < NFRAG; q++)
            #pragma unroll
            for (int e = 0; e < 4; e++) { acc1[a][q][e] = 0; accX[a][q][e] = 0; }

    auto issue = [&](int t) {
        int buf = t & 1;
        #pragma unroll
        for (int j = 0; j < 2; j++) {
            int lin = tid + j*256; int r = lin >> 2, q = lin & 3;
            uint32_t off = (uint32_t)(buf*ASZ + r*RSU + q*4) * 4;
            size_t ao = (size_t)(m0 + r)*K4 + t*16 + q*4;
            cp_async16(bA1 + off, Aq1 + ao);
            cp_async16(bA0 + off, Aq0 + ao);
        }
        {
            int r = tid >> 2, q = tid & 3;
            uint32_t off = (uint32_t)(buf*BSZ + r*RSU + q*4) * 4;
            size_t bo = (size_t)(c0 + r)*K4 + t*16 + q*4;
            cp_async16(bB1 + off, Bq1 + bo);
            cp_async16(bB0 + off, Bq0 + bo);
        }
        CP_COMMIT();
    };

    auto compute = [&](int buf) {
        #pragma unroll
        for (int kk = 0; kk < 2; kk++) {
            uint32_t a1f[2][4], a0f[2][4];
            #pragma unroll
            for (int mi = 0; mi < 2; mi++) {
                uint32_t off = (uint32_t)(buf*ASZ + (wm + mi*16 + rowA)*RSU + kk*8 + colA) * 4;
                ldsm4(a1f[mi], bA1 + off);
                ldsm4(a0f[mi], bA0 + off);
            }
            #pragma unroll
            for (int np = 0; np < NFRAG/2; np++) {
                uint32_t off = (uint32_t)(buf*BSZ + (wn + np*16 + rowB)*RSU + kk*8 + colB) * 4;
                uint32_t t1[4], t0[4];
                ldsm4(t1, bB1 + off);
                ldsm4(t0, bB0 + off);
                #pragma unroll
                for (int sub = 0; sub < 2; sub++) {
                    int ni = np*2 + sub;
                    uint32_t b1p[2] = {t1[sub*2], t1[sub*2+1]};
                    uint32_t b0p[2] = {t0[sub*2], t0[sub*2+1]};
                    #pragma unroll
                    for (int mi = 0; mi < 2; mi++) {
                        mma_s8(acc1[mi][ni], a1f[mi], b1p);
                        mma_s8(accX[mi][ni], a1f[mi], b0p);
                        mma_s8(accX[mi][ni], a0f[mi], b1p);
                    }
                }
            }
        }
    };

    const int T = K / 64;
    issue(0);
    for (int t = 0; t < T; t++) {
        CP_WAIT0();
        __syncthreads();
        if (t + 1 < T) issue(t + 1);
        compute(t & 1);
    }
    __syncthreads();

    float* sbufS  = (float*)smem_u;
    float* sbufS2 = sbufS + 4*TN;
    const float INV254 = 1.f/254.f, INVSQ = 1.f/16129.f;

    #pragma unroll
    for (int ni = 0; ni < NFRAG; ni++) {
        int col = c0 + wn + ni*8 + lk*2;
        float2 b2 = *(const float2*)(bias + col);
        float2 tc = *(const float2*)(tcol + col);
        float s0 = 0.f, s1 = 0.f, q0 = 0.f, q1 = 0.f;
        #pragma unroll
        for (int mi = 0; mi < 2; mi++) {
            int row = m0 + wm + mi*16 + l4;
            float sr0 = srow[row] * INVSQ;
            float sr1 = srow[row + 8] * INVSQ;
            float e0 = fmaf(sr0 * tc.x, (float)acc1[mi][ni][0] + (float)accX[mi][ni][0]*INV254, b2.x);
            float e1 = fmaf(sr0 * tc.y, (float)acc1[mi][ni][1] + (float)accX[mi][ni][1]*INV254, b2.y);
            float e2 = fmaf(sr1 * tc.x, (float)acc1[mi][ni][2] + (float)accX[mi][ni][2]*INV254, b2.x);
            float e3 = fmaf(sr1 * tc.y, (float)acc1[mi][ni][3] + (float)accX[mi][ni][3]*INV254, b2.y);
            *(float2*)(Y + (size_t)row * C + col)       = make_float2(e0, e1);
            *(float2*)(Y + (size_t)(row + 8) * C + col) = make_float2(e2, e3);
            s0 += e0 + e2; s1 += e1 + e3;
            q0 += e0*e0 + e2*e2; q1 += e1*e1 + e3*e3;
        }
        #pragma unroll
        for (int off = 16; off >= 4; off >>= 1) {
            s0 += __shfl_down_sync(0xffffffffu, s0, off);
            s1 += __shfl_down_sync(0xffffffffu, s1, off);
            q0 += __shfl_down_sync(0xffffffffu, q0, off);
            q1 += __shfl_down_sync(0xffffffffu, q1, off);
        }
        if (lane < 4) {
            int cb = wn + ni*8 + lk*2;
            sbufS [mw*TN + cb]     = s0;
            sbufS [mw*TN + cb + 1] = s1;
            sbufS2[mw*TN + cb]     = q0;
            sbufS2[mw*TN + cb + 1] = q1;
        }
    }
    __syncthreads();
    if (tid < TN) {
        float s = sbufS [tid] + sbufS [TN + tid] + sbufS [2*TN + tid] + sbufS [3*TN + tid];
        float q = sbufS2[tid] + sbufS2[TN + tid] + sbufS2[2*TN + tid] + sbufS2[3*TN + tid];
        pS [blockIdx.y * C + c0 + tid] = s;
        pS2[blockIdx.y * C + c0 + tid] = q;
    }
}

// ---------------- stats_final ----------------
__global__ void __launch_bounds__(256) stats_final_kernel(
    const float* __restrict__ pS, const float* __restrict__ pS2,
    const float* __restrict__ g, const float* __restrict__ bt,
    int M, int C, float* __restrict__ scale, float* __restrict__ shift)
{
    const int c = blockIdx.x * 8 + (threadIdx.x >> 5);
    const int j = threadIdx.x & 31;
    float s  = pS [j * C + c] + pS [(j + 32) * C + c];
    float s2 = pS2[j * C + c] + pS2[(j + 32) * C + c];
    #pragma unroll
    for (int off = 16; off > 0; off >>= 1) {
        s  += __shfl_down_sync(0xffffffffu, s,  off);
        s2 += __shfl_down_sync(0xffffffffu, s2, off);
    }
    if (j == 0) {
        float invM = 1.f / (float)M;
        float mean = s * invM;
        float var  = fmaf(-mean, mean, s2 * invM);
        float inv  = rsqrtf(var + EPSV);
        float scv  = g[c] * inv;
        scale[c] = scv;
        shift[c] = fmaf(-mean, scv, bt[c]);
    }
}

// ---------------- bnconvert_i8: BN+leaky -> int8 digits + row scale ----------------
// grid 1024, block 256 = 8 warps = 8 rows (C=512)
__global__ void __launch_bounds__(256) bnconvert_i8_kernel(
    const float* __restrict__ Y, const float* __restrict__ scale,
    const float* __restrict__ shift,
    uint32_t* __restrict__ q1, uint32_t* __restrict__ q0, float* __restrict__ rs)
{
    __shared__ float vals[8*512];
    const int tid = threadIdx.x;
    const int row0 = blockIdx.x * 8;

    #pragma unroll
    for (int j = 0; j < 4; j++) {
        int idx = tid + j*256;
        int r = idx >> 7, c4 = idx & 127;
        float4 y  = ((const float4*)Y)[(size_t)(row0 + r)*128 + c4];
        float4 sc = ((const float4*)scale)[c4];
        float4 sh = ((const float4*)shift)[c4];
        float4 o;
        o.x = fmaf(y.x, sc.x, sh.x); o.y = fmaf(y.y, sc.y, sh.y);
        o.z = fmaf(y.z, sc.z, sh.z); o.w = fmaf(y.w, sc.w, sh.w);
        o.x = o.x > 0.f ? o.x : o.x * SLOPE;
        o.y = o.y > 0.f ? o.y : o.y * SLOPE;
        o.z = o.z > 0.f ? o.z : o.z * SLOPE;
        o.w = o.w > 0.f ? o.w : o.w * SLOPE;
        *(float4*)&vals[r*512 + c4*4] = o;
    }
    __syncthreads();

    const int w = tid >> 5, l = tid & 31;
    const int row = row0 + w;
    float mx = 1e-20f;
    #pragma unroll
    for (int j = 0; j < 16; j++) mx = fmaxf(mx, fabsf(vals[w*512 + l + 32*j]));
    mx = warp_max(mx);
    if (l == 0) rs[row] = mx;
    float inv = 127.f / mx;
    #pragma unroll
    for (int j = 0; j < 4; j++) {
        int cu = l + 32*j;
        int d1[4], d0[4];
        #pragma unroll
        for (int e = 0; e < 4; e++) {
            float s = vals[w*512 + cu*4 + e] * inv;
            float f1 = rintf(s);
            d1[e] = (int)f1;
            d0[e] = (int)rintf((s - f1) * 254.f);
        }
        q1[(size_t)row*128 + cu] = pack4(d1);
        q0[(size_t)row*128 + cu] = pack4(d0);
    }
}

// ---------------- bnstats_apply: finalize stats + BN -> out (C=64) ----------------
__global__ void __launch_bounds__(256) bnstats_apply_kernel(
    const float* __restrict__ Y, const float* __restrict__ pS, const float* __restrict__ pS2,
    const float* __restrict__ g, const float* __restrict__ bt, float* __restrict__ out)
{
    __shared__ float ssc[64], ssh[64];
    const int tid = threadIdx.x;
    if (tid < 64) {
        float s = 0.f, q = 0.f;
        #pragma unroll 8
        for (int j = 0; j < NPART; j++) {
            s += pS [j*64 + tid];
            q += pS2[j*64 + tid];
        }
        float mean = s * (1.f/8192.f);
        float var  = fmaf(-mean, mean, q * (1.f/8192.f));
        float inv  = rsqrtf(var + EPSV);
        float scv  = g[tid] * inv;
        ssc[tid] = scv;
        ssh[tid] = fmaf(-mean, scv, bt[tid]);
    }
    __syncthreads();

    size_t base = (size_t)blockIdx.x * 2048;
    #pragma unroll 4
    for (int it = 0; it < 8; it++) {
        int idx = it*256 + tid;
        int c4 = idx & 15;
        float4 y  = ((const float4*)Y)[base + idx];
        float4 sc = ((const float4*)ssc)[c4];
        float4 sh = ((const float4*)ssh)[c4];
        float4 o;
        o.x = fmaf(y.x, sc.x, sh.x);
        o.y = fmaf(y.y, sc.y, sh.y);
        o.z = fmaf(y.z, sc.z, sh.z);
        o.w = fmaf(y.w, sc.w, sh.w);
        ((float4*)out)[base + idx] = o;
    }
}

// ---------------- host ----------------
extern "C" void kernel_launch(void* const* d_in, const int* in_sizes, int n_in,
                              void* d_out, int out_size)
{
    const float* x   = (const float*)d_in[0];
    const float* Q   = (const float*)d_in[1];
    const float* W1  = (const float*)d_in[2];
    const float* b1  = (const float*)d_in[3];
    const float* g1  = (const float*)d_in[4];
    const float* bt1 = (const float*)d_in[5];
    const float* W2  = (const float*)d_in[6];
    const float* b2  = (const float*)d_in[7];
    const float* g2  = (const float*)d_in[8];
    const float* bt2 = (const float*)d_in[9];
    const float* W3  = (const float*)d_in[10];
    const float* b3  = (const float*)d_in[11];
    const float* g3  = (const float*)d_in[12];
    const float* bt3 = (const float*)d_in[13];
    float* out = (float*)d_out;

    float *En, *Y1, *Y2, *Y3, *pS, *pS2, *scale, *shift, *tW2, *tW3, *rs;
    uint32_t *Xthi, *Xtlo, *Ghi, *Glo, *Vhi, *Vlo;
    uint32_t *W1hi, *W1lo, *W2q1, *W2q0, *W3q1, *W3q0, *Aq1, *Aq0;
    cudaGetSymbolAddress((void**)&En,   g_En);
    cudaGetSymbolAddress((void**)&Xthi, g_Xthi);  cudaGetSymbolAddress((void**)&Xtlo, g_Xtlo);
    cudaGetSymbolAddress((void**)&Ghi,  g_Ghi);   cudaGetSymbolAddress((void**)&Glo,  g_Glo);
    cudaGetSymbolAddress((void**)&Vhi,  g_Vhi);   cudaGetSymbolAddress((void**)&Vlo,  g_Vlo);
    cudaGetSymbolAddress((void**)&W1hi, g_W1hi);  cudaGetSymbolAddress((void**)&W1lo, g_W1lo);
    cudaGetSymbolAddress((void**)&W2q1, g_W2q1);  cudaGetSymbolAddress((void**)&W2q0, g_W2q0);
    cudaGetSymbolAddress((void**)&W3q1, g_W3q1);  cudaGetSymbolAddress((void**)&W3q0, g_W3q0);
    cudaGetSymbolAddress((void**)&tW2,  g_tW2);   cudaGetSymbolAddress((void**)&tW3,  g_tW3);
    cudaGetSymbolAddress((void**)&Aq1,  g_Aq1);   cudaGetSymbolAddress((void**)&Aq0,  g_Aq0);
    cudaGetSymbolAddress((void**)&rs,   g_rs);
    cudaGetSymbolAddress((void**)&Y1, g_Y1);
    cudaGetSymbolAddress((void**)&Y2, g_Y2);
    cudaGetSymbolAddress((void**)&Y3, g_Y3);
    cudaGetSymbolAddress((void**)&pS, g_pS);      cudaGetSymbolAddress((void**)&pS2, g_pS2);
    cudaGetSymbolAddress((void**)&scale, g_scale); cudaGetSymbolAddress((void**)&shift, g_shift);

    const int SMEM128 = RSU * (2*128 + 2*128) * 2 * 4;   // 81920
    const int SMEM64  = RSU * (2*128 + 2*64)  * 2 * 4;   // 61440
    cudaFuncSetAttribute(vgemm_kernel,        cudaFuncAttributeMaxDynamicSharedMemorySize, SMEM64);
    cudaFuncSetAttribute(gemm_ps_kernel<128>, cudaFuncAttributeMaxDynamicSharedMemorySize, SMEM128);
    cudaFuncSetAttribute(gemm_i8_kernel,      cudaFuncAttributeMaxDynamicSharedMemorySize, SMEM64);

    // 1) prep + buildG
    prep_kernel<<<136, 256>>>(x, Q, En, Xthi, Xtlo,
                              W1, W1hi, W1lo,
                              W2, W2q1, W2q0, tW2,
                              W3, W3q1, W3q0, tW3);
    buildG_kernel<<<128, 256>>>(x, Ghi, Glo);

    // 2) V = En .* (G @ Xt^T) - pos
    vgemm_kernel<<<dim3(4, 4, 16), 256, SMEM64>>>(Ghi, Glo, Xthi, Xtlo, En, x, Vhi, Vlo);

    // 3) layer 1 (bf16 pair, stats fused)
    gemm_ps_kernel<128><<<dim3(NH/128, MROWS/128), 256, SMEM128>>>(
        Vhi, Vlo, W1hi, W1lo, b1, Y1, pS, pS2, VDIM, NH);
    stats_final_kernel<<<NH/8, 256>>>(pS, pS2, g1, bt1, MROWS, NH, scale, shift);
    bnconvert_i8_kernel<<<1024, 256>>>(Y1, scale, shift, Aq1, Aq0, rs);

    // 4) layer 2 (int8 2-digit, stats fused)
    gemm_i8_kernel<<<dim3(NH/64, MROWS/128), 256, SMEM64>>>(
        Aq1, Aq0, W2q1, W2q0, rs, tW2, b2, Y2, pS, pS2, NH, NH);
    stats_final_kernel<<<NH/8, 256>>>(pS, pS2, g2, bt2, MROWS, NH, scale, shift);
    bnconvert_i8_kernel<<<1024, 256>>>(Y2, scale, shift, Aq1, Aq0, rs);

    // 5) layer 3 (int8 2-digit, stats fused)
    gemm_i8_kernel<<<dim3(NO/64, MROWS/128), 256, SMEM64>>>(
        Aq1, Aq0, W3q1, W3q0, rs, tW3, b3, Y3, pS, pS2, NH, NO);

    // 6) stats finalize + BN apply -> out
    bnstats_apply_kernel<<<64, 256>>>(Y3, pS, pS2, g3, bt3, out);
}

// round 10
// speedup vs baseline: 1.4204x; 1.4204x over previous
#include <cuda_runtime.h>
#include <cuda_bf16.h>
#include <cstdint>
#include <math.h>

#define BATCH 16
#define SEQ   512
#define NI    32
#define NHEAD 8
#define NH    512
#define NO    64
#define MROWS (BATCH*SEQ)      // 8192
#define VDIM  (NHEAD*NI)       // 256
#define EPSV  1e-5f
#define SLOPE 0.05f
#define NPART 64

// ---------------- scratch ----------------
__device__ float    g_En  [16*8*512];
__device__ uint32_t g_Xthi[(size_t)16*256*256], g_Xtlo[(size_t)16*256*256];
__device__ uint32_t g_Ghi [(size_t)16*512*256], g_Glo [(size_t)16*512*256];
__device__ uint32_t g_Vhi [(size_t)8192*128],   g_Vlo [(size_t)8192*128];
__device__ uint32_t g_W1hi[512*128], g_W1lo[512*128];
__device__ uint32_t g_W2hi[512*256], g_W2lo[512*256];
__device__ uint32_t g_W3hi[64*256],  g_W3lo[64*256];
__device__ uint32_t g_Axhi[(size_t)8192*256],   g_Axlo[(size_t)8192*256];
__device__ float g_Y1[(size_t)MROWS * NH];
__device__ float g_Y2[(size_t)MROWS * NH];
__device__ float g_Y3[(size_t)MROWS * NO];
__device__ float g_pS [NPART * NH];
__device__ float g_pS2[NPART * NH];
__device__ float g_scale[NH];
__device__ float g_shift[NH];

// ---------------- helpers ----------------
__device__ __forceinline__ void split_pair(float v0, float v1, uint32_t& hi, uint32_t& lo) {
    __nv_bfloat16 h0 = __float2bfloat16(v0);
    __nv_bfloat16 h1 = __float2bfloat16(v1);
    float r0 = v0 - __bfloat162float(h0);
    float r1 = v1 - __bfloat162float(h1);
    __nv_bfloat16 l0 = __float2bfloat16(r0);
    __nv_bfloat16 l1 = __float2bfloat16(r1);
    hi = ((uint32_t)__bfloat16_as_ushort(h1) << 16) | __bfloat16_as_ushort(h0);
    lo = ((uint32_t)__bfloat16_as_ushort(l1) << 16) | __bfloat16_as_ushort(l0);
}

__device__ __forceinline__ void mma_bf16(float* d, const uint32_t* a, const uint32_t* b) {
    asm volatile(
        "mma.sync.aligned.m16n8k16.row.col.f32.bf16.bf16.f32 "
        "{%0,%1,%2,%3}, {%4,%5,%6,%7}, {%8,%9}, {%0,%1,%2,%3};"
        : "+f"(d[0]), "+f"(d[1]), "+f"(d[2]), "+f"(d[3])
        : "r"(a[0]), "r"(a[1]), "r"(a[2]), "r"(a[3]), "r"(b[0]), "r"(b[1]));
}

__device__ __forceinline__ void ldsm4(uint32_t* r, uint32_t addr) {
    asm volatile("ldmatrix.sync.aligned.m8n8.x4.shared.b16 {%0,%1,%2,%3}, [%4];"
        : "=r"(r[0]), "=r"(r[1]), "=r"(r[2]), "=r"(r[3]) : "r"(addr));
}

__device__ __forceinline__ uint32_t smem_u32(const void* p) {
    uint32_t a;
    asm("{ .reg .u64 t; cvta.to.shared.u64 t, %1; cvt.u32.u64 %0, t; }" : "=r"(a) : "l"(p));
    return a;
}
__device__ __forceinline__ void cp_async16(uint32_t saddr, const void* gptr) {
    asm volatile("cp.async.cg.shared.global [%0], [%1], 16;" :: "r"(saddr), "l"(gptr));
}
#define CP_COMMIT() asm volatile("cp.async.commit_group;" ::: "memory")
#define CP_WAIT0()  asm volatile("cp.async.wait_group 0;" ::: "memory")

// ---------------- prep: En tables, Xt build, W splits ----------------
__global__ void __launch_bounds__(256) prep_kernel(
    const float* __restrict__ x, const float* __restrict__ Q,
    float* __restrict__ En,
    uint32_t* __restrict__ Xthi, uint32_t* __restrict__ Xtlo,
    const float* __restrict__ W1, uint32_t* __restrict__ W1hi, uint32_t* __restrict__ W1lo,
    const float* __restrict__ W2, uint32_t* __restrict__ W2hi, uint32_t* __restrict__ W2lo,
    const float* __restrict__ W3, uint32_t* __restrict__ W3hi, uint32_t* __restrict__ W3lo)
{
    const int blk = blockIdx.x;
    const int tid = threadIdx.x;

    if (blk >= 64) {
        int widx = blk - 64;
        const float* src; uint32_t* hi; uint32_t* lo; int base;
        if (widx < 32)      { src = W1; hi = W1hi; lo = W1lo; base = widx * 2048; }
        else if (widx < 96) { src = W2; hi = W2hi; lo = W2lo; base = (widx - 32) * 2048; }
        else                { src = W3; hi = W3hi; lo = W3lo; base = (widx - 96) * 2048; }
        int p = base + tid;
        #pragma unroll
        for (int j = 0; j < 8; j++, p += 256) {
            float2 v = ((const float2*)src)[p];
            uint32_t h, l; split_pair(v.x, v.y, h, l);
            hi[p] = h; lo[p] = l;
        }
        return;
    }

    const int b = blk >> 2, chunk = blk & 3;

    __shared__ float sEm[8][128];
    __shared__ float sQ[8][4];
    __shared__ uint32_t shi[256][8], slo[256][8];

    if (tid < 8) {
        float a = Q[tid*3+0], bq = Q[tid*3+1], cq = Q[tid*3+2];
        sQ[tid][0] = a; sQ[tid][1] = bq; sQ[tid][2] = cq;
        sQ[tid][3] = a*a + bq*bq + cq*cq;
    }
    __syncthreads();

    if (tid < 128) {
        int m = chunk*128 + tid;
        const float* xp = x + ((size_t)b*512 + m)*32;
        float px = xp[0], py = xp[1], pz = xp[2];
        #pragma unroll
        for (int h = 0; h < 8; h++) {
            float dot = px*sQ[h][0] + py*sQ[h][1] + pz*sQ[h][2];
            float em = __expf(-2.f*dot);
            float en = __expf(2.f*dot - sQ[h][3]);
            sEm[h][tid] = em;
            En[((size_t)b*8 + h)*512 + m] = en;
        }
    }
    __syncthreads();

    const int c = tid, h = c >> 5, i = c & 31;
    for (int grp = 0; grp < 8; grp++) {
        #pragma unroll
        for (int j = 0; j < 8; j++) {
            int mloc = (grp*8 + j)*2;
            int m = chunk*128 + mloc;
            float v0 = sEm[h][mloc]   * x[((size_t)b*512 + m  )*32 + i];
            float v1 = sEm[h][mloc+1] * x[((size_t)b*512 + m+1)*32 + i];
            uint32_t hh, ll; split_pair(v0, v1, hh, ll);
            shi[c][j] = hh; slo[c][j] = ll;
        }
        __syncthreads();
        int cc = tid >> 3, j2 = tid & 7;
        #pragma unroll
        for (int rep = 0; rep < 8; rep++) {
            int ccc = cc + rep*32;
            size_t addr = ((size_t)b*256 + ccc)*256 + chunk*64 + grp*8 + j2;
            Xthi[addr] = shi[ccc][j2];
            Xtlo[addr] = slo[ccc][j2];
        }
        __syncthreads();
    }
}

// ---------------- buildG ----------------
__global__ void __launch_bounds__(256) buildG_kernel(
    const float* __restrict__ x, uint32_t* __restrict__ Ghi, uint32_t* __restrict__ Glo)
{
    const int b  = blockIdx.x >> 3, nt = blockIdx.x & 7;
    const int tid = threadIdx.x;
    const int n = tid & 63, mq = tid >> 6;

    __shared__ float pn3[64][5];
    __shared__ float pm3[128][4];

    if (tid < 64) {
        const float* xp = x + ((size_t)b*512 + nt*64 + tid)*32;
        pn3[tid][0] = xp[0]; pn3[tid][1] = xp[1]; pn3[tid][2] = xp[2];
    }

    for (int mc = 0; mc < 4; mc++) {
        __syncthreads();
        if (tid < 128) {
            const float* xp = x + ((size_t)b*512 + mc*128 + tid)*32;
            pm3[tid][0] = xp[0]; pm3[tid][1] = xp[1]; pm3[tid][2] = xp[2];
        }
        __syncthreads();
        float px = pn3[n][0], py = pn3[n][1], pz = pn3[n][2];
        uint32_t outh[16], outl[16];
        #pragma unroll
        for (int j = 0; j < 16; j++) {
            int ml = mq*32 + j*2;
            float dx0 = px - pm3[ml][0],   dy0 = py - pm3[ml][1],   dz0 = pz - pm3[ml][2];
            float dx1 = px - pm3[ml+1][0], dy1 = py - pm3[ml+1][1], dz1 = pz - pm3[ml+1][2];
            float e0 = __expf(-(dx0*dx0 + dy0*dy0 + dz0*dz0));
            float e1 = __expf(-(dx1*dx1 + dy1*dy1 + dz1*dz1));
            split_pair(e0, e1, outh[j], outl[j]);
        }
        size_t base = ((size_t)b*512 + nt*64 + n)*256 + mc*64 + mq*16;
        #pragma unroll
        for (int j4 = 0; j4 < 4; j4++) {
            ((uint4*)(Ghi + base))[j4] = make_uint4(outh[j4*4], outh[j4*4+1], outh[j4*4+2], outh[j4*4+3]);
            ((uint4*)(Glo + base))[j4] = make_uint4(outl[j4*4], outl[j4*4+1], outl[j4*4+2], outl[j4*4+3]);
        }
    }
}

// ================= GEMM machinery: TN=64, K32, 2-stage, ldsm, RSU=20 =================
#define RSU 20
#define TN  64
#define NFRAG (TN/16)
#define ASZ (128*RSU)
#define BSZ (TN*RSU)

// ---------------- vgemm: V = En .* (G @ Xt^T) - pos ----------------
__global__ void __launch_bounds__(256, 3) vgemm_kernel(
    const uint32_t* __restrict__ Ghi, const uint32_t* __restrict__ Glo,
    const uint32_t* __restrict__ Bhi_g, const uint32_t* __restrict__ Blo_g,
    const float* __restrict__ En, const float* __restrict__ x,
    uint32_t* __restrict__ Vhi, uint32_t* __restrict__ Vlo)
{
    constexpr int KE = 512, K2 = KE/2;
    extern __shared__ uint32_t smem_u[];
    const uint32_t sbase = smem_u32(smem_u);
    const uint32_t bAh = sbase;
    const uint32_t bAl = sbase + 2*ASZ*4;
    const uint32_t bBh = sbase + 4*ASZ*4;
    const uint32_t bBl = sbase + (4*ASZ + 2*BSZ)*4;

    const int tid = threadIdx.x, wid = tid >> 5, lane = tid & 31;
    const int wm = (wid >> 1) * 32, wn = (wid & 1) * (TN/2);
    const int l4 = lane >> 2, lk = lane & 3;
    const int rowA = lane & 15, colA = (lane >> 4) * 4;
    const int rowB = ((lane >> 4) & 1) * 8 + (lane & 7);
    const int colB = ((lane >> 3) & 1) * 4;
    const int b = blockIdx.z;
    const int m0 = blockIdx.y * 128, c0 = blockIdx.x * TN;

    const uint32_t* Ah_g = Ghi + (size_t)b*512*K2;
    const uint32_t* Al_g = Glo + (size_t)b*512*K2;
    const uint32_t* Bh_g = Bhi_g + (size_t)b*256*K2;
    const uint32_t* Bl_g = Blo_g + (size_t)b*256*K2;

    float acc[2][NFRAG][4];
    #pragma unroll
    for (int a = 0; a < 2; a++)
        #pragma unroll
        for (int q = 0; q < NFRAG; q++)
            { acc[a][q][0]=0.f; acc[a][q][1]=0.f; acc[a][q][2]=0.f; acc[a][q][3]=0.f; }

    auto issue = [&](int t) {
        int buf = t & 1;
        #pragma unroll
        for (int j = 0; j < 2; j++) {
            int lin = tid + j*256; int r = lin >> 2, q = lin & 3;
            uint32_t off = (uint32_t)(buf*ASZ + r*RSU + q*4) * 4;
            size_t ao = (size_t)(m0 + r)*K2 + t*16 + q*4;
            cp_async16(bAh + off, Ah_g + ao);
            cp_async16(bAl + off, Al_g + ao);
        }
        {
            int r = tid >> 2, q = tid & 3;
            uint32_t off = (uint32_t)(buf*BSZ + r*RSU + q*4) * 4;
            size_t bo = (size_t)(c0 + r)*K2 + t*16 + q*4;
            cp_async16(bBh + off, Bh_g + bo);
            cp_async16(bBl + off, Bl_g + bo);
        }
        CP_COMMIT();
    };

    auto compute = [&](int buf) {
        #pragma unroll
        for (int kk = 0; kk < 2; kk++) {
            uint32_t ah[2][4], al[2][4];
            #pragma unroll
            for (int mi = 0; mi < 2; mi++) {
                uint32_t off = (uint32_t)(buf*ASZ + (wm + mi*16 + rowA)*RSU + kk*8 + colA) * 4;
                ldsm4(ah[mi], bAh + off);
                ldsm4(al[mi], bAl + off);
            }
            #pragma unroll
            for (int np = 0; np < NFRAG/2; np++) {
                uint32_t off = (uint32_t)(buf*BSZ + (wn + np*16 + rowB)*RSU + kk*8 + colB) * 4;
                uint32_t th[4], tl[4];
                ldsm4(th, bBh + off);
                ldsm4(tl, bBl + off);
                #pragma unroll
                for (int sub = 0; sub < 2; sub++) {
                    int ni = np*2 + sub;
                    uint32_t bhp[2] = {th[sub*2], th[sub*2+1]};
                    uint32_t blp[2] = {tl[sub*2], tl[sub*2+1]};
                    #pragma unroll
                    for (int mi = 0; mi < 2; mi++) {
                        mma_bf16(acc[mi][ni], ah[mi], bhp);
                        mma_bf16(acc[mi][ni], ah[mi], blp);
                        mma_bf16(acc[mi][ni], al[mi], bhp);
                    }
                }
            }
        }
    };

    const int T = KE / 32;
    issue(0);
    for (int t = 0; t < T; t++) {
        CP_WAIT0();
        __syncthreads();
        if (t + 1 < T) issue(t + 1);
        compute(t & 1);
    }

    #pragma unroll
    for (int mi = 0; mi < 2; mi++) {
        #pragma unroll
        for (int ni = 0; ni < NFRAG; ni++) {
            int n0 = m0 + wm + mi*16 + l4;
            int cc = c0 + wn + ni*8 + lk*2;
            int h = cc >> 5, il = cc & 31;
            float en0 = En[((size_t)b*8 + h)*512 + n0];
            float en1 = En[((size_t)b*8 + h)*512 + n0 + 8];
            float v00 = acc[mi][ni][0]*en0, v01 = acc[mi][ni][1]*en0;
            float v10 = acc[mi][ni][2]*en1, v11 = acc[mi][ni][3]*en1;
            if (il < 3) {
                v00 -= x[((size_t)b*512 + n0  )*32 + il];
                v10 -= x[((size_t)b*512 + n0+8)*32 + il];
            }
            if (il + 1 < 3) {
                v01 -= x[((size_t)b*512 + n0  )*32 + il + 1];
                v11 -= x[((size_t)b*512 + n0+8)*32 + il + 1];
            }
            uint32_t h0, l0, h1, l1;
            split_pair(v00, v01, h0, l0);
            split_pair(v10, v11, h1, l1);
            size_t r0 = ((size_t)b*512 + n0)*128 + (cc >> 1);
            size_t r1 = ((size_t)b*512 + n0 + 8)*128 + (cc >> 1);
            Vhi[r0] = h0; Vlo[r0] = l0;
            Vhi[r1] = h1; Vlo[r1] = l1;
        }
    }
}

// ---------------- gemm_ps (bf16 pair, TN=64) + fused column stats ----------------
__global__ void __launch_bounds__(256, 3) gemm_ps_kernel(
    const uint32_t* __restrict__ Ah_g, const uint32_t* __restrict__ Al_g,
    const uint32_t* __restrict__ Bh_g, const uint32_t* __restrict__ Bl_g,
    const float* __restrict__ bias, float* __restrict__ Y,
    float* __restrict__ pS, float* __restrict__ pS2, int K, int C)
{
    extern __shared__ uint32_t smem_u[];
    const uint32_t sbase = smem_u32(smem_u);
    const uint32_t bAh = sbase;
    const uint32_t bAl = sbase + 2*ASZ*4;
    const uint32_t bBh = sbase + 4*ASZ*4;
    const uint32_t bBl = sbase + (4*ASZ + 2*BSZ)*4;

    const int tid = threadIdx.x, wid = tid >> 5, lane = tid & 31;
    const int wm = (wid >> 1) * 32, wn = (wid & 1) * (TN/2);
    const int mw = wid >> 1;
    const int l4 = lane >> 2, lk = lane & 3;
    const int rowA = lane & 15, colA = (lane >> 4) * 4;
    const int rowB = ((lane >> 4) & 1) * 8 + (lane & 7);
    const int colB = ((lane >> 3) & 1) * 4;
    const int m0 = blockIdx.y * 128, c0 = blockIdx.x * TN;
    const int K2 = K >> 1;

    float acc[2][NFRAG][4];
    #pragma unroll
    for (int a = 0; a < 2; a++)
        #pragma unroll
        for (int q = 0; q < NFRAG; q++)
            { acc[a][q][0]=0.f; acc[a][q][1]=0.f; acc[a][q][2]=0.f; acc[a][q][3]=0.f; }

    auto issue = [&](int t) {
        int buf = t & 1;
        #pragma unroll
        for (int j = 0; j < 2; j++) {
            int lin = tid + j*256; int r = lin >> 2, q = lin & 3;
            uint32_t off = (uint32_t)(buf*ASZ + r*RSU + q*4) * 4;
            size_t ao = (size_t)(m0 + r)*K2 + t*16 + q*4;
            cp_async16(bAh + off, Ah_g + ao);
            cp_async16(bAl + off, Al_g + ao);
        }
        {
            int r = tid >> 2, q = tid & 3;
            uint32_t off = (uint32_t)(buf*BSZ + r*RSU + q*4) * 4;
            size_t bo = (size_t)(c0 + r)*K2 + t*16 + q*4;
            cp_async16(bBh + off, Bh_g + bo);
            cp_async16(bBl + off, Bl_g + bo);
        }
        CP_COMMIT();
    };

    auto compute = [&](int buf) {
        #pragma unroll
        for (int kk = 0; kk < 2; kk++) {
            uint32_t ah[2][4], al[2][4];
            #pragma unroll
            for (int mi = 0; mi < 2; mi++) {
                uint32_t off = (uint32_t)(buf*ASZ + (wm + mi*16 + rowA)*RSU + kk*8 + colA) * 4;
                ldsm4(ah[mi], bAh + off);
                ldsm4(al[mi], bAl + off);
            }
            #pragma unroll
            for (int np = 0; np < NFRAG/2; np++) {
                uint32_t off = (uint32_t)(buf*BSZ + (wn + np*16 + rowB)*RSU + kk*8 + colB) * 4;
                uint32_t th[4], tl[4];
                ldsm4(th, bBh + off);
                ldsm4(tl, bBl + off);
                #pragma unroll
                for (int sub = 0; sub < 2; sub++) {
                    int ni = np*2 + sub;
                    uint32_t bhp[2] = {th[sub*2], th[sub*2+1]};
                    uint32_t blp[2] = {tl[sub*2], tl[sub*2+1]};
                    #pragma unroll
                    for (int mi = 0; mi < 2; mi++) {
                        mma_bf16(acc[mi][ni], ah[mi], bhp);
                        mma_bf16(acc[mi][ni], ah[mi], blp);
                        mma_bf16(acc[mi][ni], al[mi], bhp);
                    }
                }
            }
        }
    };

    const int T = K / 32;
    issue(0);
    for (int t = 0; t < T; t++) {
        CP_WAIT0();
        __syncthreads();
        if (t + 1 < T) issue(t + 1);
        compute(t & 1);
    }
    __syncthreads();   // smem reused for stats below

    float* sbufS  = (float*)smem_u;
    float* sbufS2 = sbufS + 4*TN;

    #pragma unroll
    for (int ni = 0; ni < NFRAG; ni++) {
        int col = c0 + wn + ni*8 + lk*2;
        float2 b2 = *(const float2*)(bias + col);
        float s0 = 0.f, s1 = 0.f, q0 = 0.f, q1 = 0.f;
        #pragma unroll
        for (int mi = 0; mi < 2; mi++) {
            int row = m0 + wm + mi*16 + l4;
            float e0 = acc[mi][ni][0] + b2.x;
            float e1 = acc[mi][ni][1] + b2.y;
            float e2 = acc[mi][ni][2] + b2.x;
            float e3 = acc[mi][ni][3] + b2.y;
            *(float2*)(Y + (size_t)row * C + col)       = make_float2(e0, e1);
            *(float2*)(Y + (size_t)(row + 8) * C + col) = make_float2(e2, e3);
            s0 += e0 + e2; s1 += e1 + e3;
            q0 += e0*e0 + e2*e2; q1 += e1*e1 + e3*e3;
        }
        #pragma unroll
        for (int off = 16; off >= 4; off >>= 1) {
            s0 += __shfl_down_sync(0xffffffffu, s0, off);
            s1 += __shfl_down_sync(0xffffffffu, s1, off);
            q0 += __shfl_down_sync(0xffffffffu, q0, off);
            q1 += __shfl_down_sync(0xffffffffu, q1, off);
        }
        if (lane < 4) {
            int cb = wn + ni*8 + lk*2;
            sbufS [mw*TN + cb]     = s0;
            sbufS [mw*TN + cb + 1] = s1;
            sbufS2[mw*TN + cb]     = q0;
            sbufS2[mw*TN + cb + 1] = q1;
        }
    }
    __syncthreads();
    if (tid < TN) {
        float s = sbufS [tid] + sbufS [TN + tid] + sbufS [2*TN + tid] + sbufS [3*TN + tid];
        float q = sbufS2[tid] + sbufS2[TN + tid] + sbufS2[2*TN + tid] + sbufS2[3*TN + tid];
        pS [blockIdx.y * C + c0 + tid] = s;
        pS2[blockIdx.y * C + c0 + tid] = q;
    }
}

// ---------------- stats_final ----------------
__global__ void __launch_bounds__(256) stats_final_kernel(
    const float* __restrict__ pS, const float* __restrict__ pS2,
    const float* __restrict__ g, const float* __restrict__ bt,
    int M, int C, float* __restrict__ scale, float* __restrict__ shift)
{
    const int c = blockIdx.x * 8 + (threadIdx.x >> 5);
    const int j = threadIdx.x & 31;
    float s  = pS [j * C + c] + pS [(j + 32) * C + c];
    float s2 = pS2[j * C + c] + pS2[(j + 32) * C + c];
    #pragma unroll
    for (int off = 16; off > 0; off >>= 1) {
        s  += __shfl_down_sync(0xffffffffu, s,  off);
        s2 += __shfl_down_sync(0xffffffffu, s2, off);
    }
    if (j == 0) {
        float invM = 1.f / (float)M;
        float mean = s * invM;
        float var  = fmaf(-mean, mean, s2 * invM);
        float inv  = rsqrtf(var + EPSV);
        float scv  = g[c] * inv;
        scale[c] = scv;
        shift[c] = fmaf(-mean, scv, bt[c]);
    }
}

// ---------------- bnconvert: Y fp32 -> leaky(BN(Y)) -> split bf16 ----------------
__global__ void __launch_bounds__(256) bnconvert_kernel(
    const float* __restrict__ Y, const float* __restrict__ scale,
    const float* __restrict__ shift, uint32_t* __restrict__ hi, uint32_t* __restrict__ lo,
    int total4, int C4)
{
    int idx = blockIdx.x * blockDim.x + threadIdx.x;
    if (idx >= total4) return;
    int c4 = idx % C4;
    float4 y  = ((const float4*)Y)[idx];
    float4 sc = ((const float4*)scale)[c4];
    float4 sh = ((const float4*)shift)[c4];
    float v[4];
    v[0] = fmaf(y.x, sc.x, sh.x); v[1] = fmaf(y.y, sc.y, sh.y);
    v[2] = fmaf(y.z, sc.z, sh.z); v[3] = fmaf(y.w, sc.w, sh.w);
    #pragma unroll
    for (int q = 0; q < 4; q++) v[q] = v[q] > 0.f ? v[q] : v[q] * SLOPE;
    uint32_t h0, l0, h1, l1;
    split_pair(v[0], v[1], h0, l0);
    split_pair(v[2], v[3], h1, l1);
    ((uint2*)hi)[idx] = make_uint2(h0, h1);
    ((uint2*)lo)[idx] = make_uint2(l0, l1);
}

// ---------------- final BN apply ----------------
__global__ void __launch_bounds__(256) bnapply_kernel(
    const float* __restrict__ Y, const float* __restrict__ scale,
    const float* __restrict__ shift, float* __restrict__ out, int total4, int C4)
{
    int idx = blockIdx.x * blockDim.x + threadIdx.x;
    if (idx >= total4) return;
    int c4 = idx % C4;
    float4 y  = ((const float4*)Y)[idx];
    float4 sc = ((const float4*)scale)[c4];
    float4 sh = ((const float4*)shift)[c4];
    float4 o;
    o.x = fmaf(y.x, sc.x, sh.x);
    o.y = fmaf(y.y, sc.y, sh.y);
    o.z = fmaf(y.z, sc.z, sh.z);
    o.w = fmaf(y.w, sc.w, sh.w);
    ((float4*)out)[idx] = o;
}

// ---------------- host ----------------
extern "C" void kernel_launch(void* const* d_in, const int* in_sizes, int n_in,
                              void* d_out, int out_size)
{
    const float* x   = (const float*)d_in[0];
    const float* Q   = (const float*)d_in[1];
    const float* W1  = (const float*)d_in[2];
    const float* b1  = (const float*)d_in[3];
    const float* g1  = (const float*)d_in[4];
    const float* bt1 = (const float*)d_in[5];
    const float* W2  = (const float*)d_in[6];
    const float* b2  = (const float*)d_in[7];
    const float* g2  = (const float*)d_in[8];
    const float* bt2 = (const float*)d_in[9];
    const float* W3  = (const float*)d_in[10];
    const float* b3  = (const float*)d_in[11];
    const float* g3  = (const float*)d_in[12];
    const float* bt3 = (const float*)d_in[13];
    float* out = (float*)d_out;

    float *En, *Y1, *Y2, *Y3, *pS, *pS2, *scale, *shift;
    uint32_t *Xthi, *Xtlo, *Ghi, *Glo, *Vhi, *Vlo, *Axhi, *Axlo;
    uint32_t *W1hi, *W1lo, *W2hi, *W2lo, *W3hi, *W3lo;
    cudaGetSymbolAddress((void**)&En,   g_En);
    cudaGetSymbolAddress((void**)&Xthi, g_Xthi);  cudaGetSymbolAddress((void**)&Xtlo, g_Xtlo);
    cudaGetSymbolAddress((void**)&Ghi,  g_Ghi);   cudaGetSymbolAddress((void**)&Glo,  g_Glo);
    cudaGetSymbolAddress((void**)&Vhi,  g_Vhi);   cudaGetSymbolAddress((void**)&Vlo,  g_Vlo);
    cudaGetSymbolAddress((void**)&Axhi, g_Axhi);  cudaGetSymbolAddress((void**)&Axlo, g_Axlo);
    cudaGetSymbolAddress((void**)&W1hi, g_W1hi);  cudaGetSymbolAddress((void**)&W1lo, g_W1lo);
    cudaGetSymbolAddress((void**)&W2hi, g_W2hi);  cudaGetSymbolAddress((void**)&W2lo, g_W2lo);
    cudaGetSymbolAddress((void**)&W3hi, g_W3hi);  cudaGetSymbolAddress((void**)&W3lo, g_W3lo);
    cudaGetSymbolAddress((void**)&Y1, g_Y1);
    cudaGetSymbolAddress((void**)&Y2, g_Y2);
    cudaGetSymbolAddress((void**)&Y3, g_Y3);
    cudaGetSymbolAddress((void**)&pS, g_pS);      cudaGetSymbolAddress((void**)&pS2, g_pS2);
    cudaGetSymbolAddress((void**)&scale, g_scale); cudaGetSymbolAddress((void**)&shift, g_shift);

    const int SMEM64 = RSU * (2*128 + 2*64) * 2 * 4;   // 61440 B
    cudaFuncSetAttribute(vgemm_kernel,   cudaFuncAttributeMaxDynamicSharedMemorySize, SMEM64);
    cudaFuncSetAttribute(gemm_ps_kernel, cudaFuncAttributeMaxDynamicSharedMemorySize, SMEM64);

    // 1) prep + buildG
    prep_kernel<<<168, 256>>>(x, Q, En, Xthi, Xtlo,
                              W1, W1hi, W1lo, W2, W2hi, W2lo, W3, W3hi, W3lo);
    buildG_kernel<<<128, 256>>>(x, Ghi, Glo);

    // 2) V = En .* (G @ Xt^T) - pos
    vgemm_kernel<<<dim3(4, 4, 16), 256, SMEM64>>>(Ghi, Glo, Xthi, Xtlo, En, x, Vhi, Vlo);

    // 3) layer 1 (stats fused)
    gemm_ps_kernel<<<dim3(NH/64, MROWS/128), 256, SMEM64>>>(
        Vhi, Vlo, W1hi, W1lo, b1, Y1, pS, pS2, VDIM, NH);
    stats_final_kernel<<<NH/8, 256>>>(pS, pS2, g1, bt1, MROWS, NH, scale, shift);
    bnconvert_kernel<<<(MROWS*NH/4 + 255)/256, 256>>>(Y1, scale, shift, Axhi, Axlo, MROWS*NH/4, NH/4);

    // 4) layer 2
    gemm_ps_kernel<<<dim3(NH/64, MROWS/128), 256, SMEM64>>>(
        Axhi, Axlo, W2hi, W2lo, b2, Y2, pS, pS2, NH, NH);
    stats_final_kernel<<<NH/8, 256>>>(pS, pS2, g2, bt2, MROWS, NH, scale, shift);
    bnconvert_kernel<<<(MROWS*NH/4 + 255)/256, 256>>>(Y2, scale, shift, Axhi, Axlo, MROWS*NH/4, NH/4);

    // 5) layer 3
    gemm_ps_kernel<<<dim3(NO/64, MROWS/128), 256, SMEM64>>>(
        Axhi, Axlo, W3hi, W3lo, b3, Y3, pS, pS2, NH, NO);
    stats_final_kernel<<<NO/8, 256>>>(pS, pS2, g3, bt3, MROWS, NO, scale, shift);

    // 6) final BN apply -> out
    int total4 = MROWS * NO / 4;
    bnapply_kernel<<<(total4 + 255)/256, 256>>>(Y3, scale, shift, out, total4, NO/4);
}